// round 4
// baseline (speedup 1.0000x reference)
#include <cuda_runtime.h>

#define NNODES 50000
#define NEDGES 1600000

// ---------------- scratch (no allocations allowed) ----------------
__device__ float g_u [NNODES * 128];
__device__ float g_s [NNODES * 128];
__device__ float g_h1[NNODES * 128];
__device__ float g_h2[NNODES * 128];
__device__ float g_p [NNODES * 128];
__device__ float g_q [NNODES * 128];
__device__ int   g_cnt[NNODES];
__device__ float g_inv[NNODES];
// CSR (built once per call, reused by both layers)
__device__ int   g_bsum[256];
__device__ int   g_boff[256];
__device__ int   g_off [NNODES];
__device__ int   g_pos [NNODES];
__device__ int   g_eid [NEDGES];
__device__ int   g_esrc[NEDGES];

// ---------------- packed f32x2 helpers ----------------
__device__ __forceinline__ unsigned long long fma2(unsigned long long a,
                                                   unsigned long long b,
                                                   unsigned long long c) {
    unsigned long long d;
    asm("fma.rn.f32x2 %0, %1, %2, %3;" : "=l"(d) : "l"(a), "l"(b), "l"(c));
    return d;
}
__device__ __forceinline__ unsigned long long pack2(float x, float y) {
    unsigned long long d;
    asm("mov.b64 %0, {%1, %2};" : "=l"(d) : "f"(x), "f"(y));
    return d;
}
__device__ __forceinline__ float2 unpack2(unsigned long long v) {
    float2 r;
    asm("mov.b64 {%0, %1}, %2;" : "=f"(r.x), "=f"(r.y) : "l"(v));
    return r;
}

// ---------------- CSR build ----------------
__global__ void k_zero_cnt() {
    int i = blockIdx.x * blockDim.x + threadIdx.x;
    if (i < NNODES) g_cnt[i] = 0;
}
__global__ void k_count(const int* __restrict__ dst) {
    int e = blockIdx.x * blockDim.x + threadIdx.x;          // exactly NEDGES threads
    atomicAdd(&g_cnt[dst[e]], 1);
}
__global__ void k_scan1() {
    __shared__ int sh[256];
    int i = blockIdx.x * 256 + threadIdx.x;
    int v = (i < NNODES) ? g_cnt[i] : 0;
    sh[threadIdx.x] = v; __syncthreads();
    for (int o = 128; o > 0; o >>= 1) {
        if (threadIdx.x < o) sh[threadIdx.x] += sh[threadIdx.x + o];
        __syncthreads();
    }
    if (threadIdx.x == 0) g_bsum[blockIdx.x] = sh[0];
}
__global__ void k_scan2(int nblk) {
    __shared__ int sh[256];
    int t = threadIdx.x;
    int v = (t < nblk) ? g_bsum[t] : 0;
    sh[t] = v; __syncthreads();
    for (int o = 1; o < 256; o <<= 1) {
        int x = (t >= o) ? sh[t - o] : 0;
        __syncthreads();
        sh[t] += x;
        __syncthreads();
    }
    g_boff[t] = sh[t] - v;                                  // exclusive
}
__global__ void k_scan3() {
    __shared__ int sh[256];
    int i = blockIdx.x * 256 + threadIdx.x;
    int t = threadIdx.x;
    int v = (i < NNODES) ? g_cnt[i] : 0;
    sh[t] = v; __syncthreads();
    for (int o = 1; o < 256; o <<= 1) {
        int x = (t >= o) ? sh[t - o] : 0;
        __syncthreads();
        sh[t] += x;
        __syncthreads();
    }
    int excl = sh[t] - v + g_boff[blockIdx.x];
    if (i < NNODES) {
        g_off[i] = excl;
        g_pos[i] = excl;
        g_inv[i] = 1.0f / fmaxf((float)v, 1.0f);
    }
}
__global__ void k_scatter(const int* __restrict__ src, const int* __restrict__ dst) {
    int e = blockIdx.x * blockDim.x + threadIdx.x;          // exactly NEDGES threads
    int d = dst[e];
    int pos = atomicAdd(&g_pos[d], 1);
    g_eid [pos] = e;
    g_esrc[pos] = src[e];
}

// ---------------- node GEMM: C = act( [A1 | A2] @ W + bias ) ----------------
__global__ void __launch_bounds__(256)
k_gemm(const float* __restrict__ A1, int K1,
       const float* __restrict__ A2, int K2,
       const float* __restrict__ W, const float* __restrict__ bias,
       float* __restrict__ C, int doRelu)
{
    __shared__ float Ash[32][65];
    __shared__ unsigned long long Wshp[32][64];

    const int tid  = threadIdx.x;
    const int cg   = tid & 15;
    const int rg   = tid >> 4;
    const int col0 = cg << 3;
    const int row0 = rg << 2;
    const int n0   = blockIdx.x * 64;
    const int Ktot = K1 + K2;

    unsigned long long acc[4][4];
    #pragma unroll
    for (int i = 0; i < 4; ++i)
        #pragma unroll
        for (int t = 0; t < 4; ++t) acc[i][t] = 0ull;

    for (int kb = 0; kb < Ktot; kb += 32) {
        #pragma unroll
        for (int l = 0; l < 8; ++l) {
            int e  = tid + l * 256;
            int nd = e >> 5, k = e & 31;
            int gn = n0 + nd, gk = kb + k;
            float v = 0.f;
            if (gn < NNODES) {
                if (gk < K1) v = A1[(size_t)gn * K1 + gk];
                else         v = A2[(size_t)gn * K2 + (gk - K1)];
            }
            Ash[k][nd] = v;
        }
        #pragma unroll
        for (int l = 0; l < 8; ++l) {
            int e = tid + l * 256;
            int k = e >> 6, cp = e & 63;
            Wshp[k][cp] =
                reinterpret_cast<const unsigned long long*>(W + (size_t)(kb + k) * 128)[cp];
        }
        __syncthreads();

        #pragma unroll
        for (int k = 0; k < 32; ++k) {
            float a0 = Ash[k][row0 + 0];
            float a1 = Ash[k][row0 + 1];
            float a2 = Ash[k][row0 + 2];
            float a3 = Ash[k][row0 + 3];
            unsigned long long p0 = pack2(a0, a0);
            unsigned long long p1 = pack2(a1, a1);
            unsigned long long p2 = pack2(a2, a2);
            unsigned long long p3 = pack2(a3, a3);
            ulonglong2 w0 = *reinterpret_cast<const ulonglong2*>(&Wshp[k][cg * 4]);
            ulonglong2 w1 = *reinterpret_cast<const ulonglong2*>(&Wshp[k][cg * 4 + 2]);
            acc[0][0] = fma2(p0, w0.x, acc[0][0]); acc[0][1] = fma2(p0, w0.y, acc[0][1]);
            acc[0][2] = fma2(p0, w1.x, acc[0][2]); acc[0][3] = fma2(p0, w1.y, acc[0][3]);
            acc[1][0] = fma2(p1, w0.x, acc[1][0]); acc[1][1] = fma2(p1, w0.y, acc[1][1]);
            acc[1][2] = fma2(p1, w1.x, acc[1][2]); acc[1][3] = fma2(p1, w1.y, acc[1][3]);
            acc[2][0] = fma2(p2, w0.x, acc[2][0]); acc[2][1] = fma2(p2, w0.y, acc[2][1]);
            acc[2][2] = fma2(p2, w1.x, acc[2][2]); acc[2][3] = fma2(p2, w1.y, acc[2][3]);
            acc[3][0] = fma2(p3, w0.x, acc[3][0]); acc[3][1] = fma2(p3, w0.y, acc[3][1]);
            acc[3][2] = fma2(p3, w1.x, acc[3][2]); acc[3][3] = fma2(p3, w1.y, acc[3][3]);
        }
        __syncthreads();
    }

    float bv[8];
    #pragma unroll
    for (int t = 0; t < 8; ++t) bv[t] = bias ? bias[col0 + t] : 0.f;

    #pragma unroll
    for (int i = 0; i < 4; ++i) {
        int gn = n0 + row0 + i;
        if (gn >= NNODES) continue;
        float2 v0 = unpack2(acc[i][0]);
        float2 v1 = unpack2(acc[i][1]);
        float2 v2 = unpack2(acc[i][2]);
        float2 v3 = unpack2(acc[i][3]);
        float o[8] = { v0.x + bv[0], v0.y + bv[1], v1.x + bv[2], v1.y + bv[3],
                       v2.x + bv[4], v2.y + bv[5], v3.x + bv[6], v3.y + bv[7] };
        if (doRelu) {
            #pragma unroll
            for (int t = 0; t < 8; ++t) o[t] = fmaxf(o[t], 0.f);
        }
        float* cp = &C[(size_t)gn * 128 + col0];
        *reinterpret_cast<float4*>(cp)     = make_float4(o[0], o[1], o[2], o[3]);
        *reinterpret_cast<float4*>(cp + 4) = make_float4(o[4], o[5], o[6], o[7]);
    }
}

// ---------------- gather-mean aggregation (CSR), register-cached weights ----
// one warp per dst node: s[v] = mean_e relu(u[src_e] + efeats[e] @ We)
// Each lane owns 4 output columns; all 32 k-slices of We live in registers.
__global__ void __launch_bounds__(128)
k_aggr(const float* __restrict__ efeats, const float* __restrict__ We,
       const float* __restrict__ u, float* __restrict__ s)
{
    __shared__ unsigned long long WeP[32][64];         // staging for reg fill (16KB)
    __shared__ unsigned long long Esh[4][8][32];       // [warp][edge][k] dup-pair (8KB)

    const int tid  = threadIdx.x;
    const int wid  = tid >> 5;
    const int lane = tid & 31;

    #pragma unroll
    for (int l = 0; l < 16; ++l) {
        int e = tid + l * 128;
        int k = e >> 6, cp = e & 63;
        WeP[k][cp] =
            reinterpret_cast<const unsigned long long*>(We + (size_t)k * 128)[cp];
    }
    __syncthreads();

    // register-cache: lane owns cols [4*lane, 4*lane+4)
    ulonglong2 wreg[32];
    #pragma unroll
    for (int k = 0; k < 32; ++k)
        wreg[k] = *reinterpret_cast<const ulonglong2*>(&WeP[k][lane * 2]);

    const int v    = blockIdx.x * 4 + wid;             // exact: N = 12500*4
    const int deg  = g_cnt[v];
    const int base = g_off[v];

    float a0 = 0.f, a1 = 0.f, a2 = 0.f, a3 = 0.f;

    for (int g = 0; g < deg; g += 8) {
        const int nr = (deg - g < 8) ? (deg - g) : 8;
        int eid = 0, sr = 0;
        if (lane < nr) {
            eid = g_eid [base + g + lane];
            sr  = g_esrc[base + g + lane];
        }
        // stage e: lane covers edge r=lane>>2, k-range [8*(lane&3), +8)
        {
            int r  = lane >> 2;
            int qt = lane & 3;
            int er = __shfl_sync(0xffffffffu, eid, r);
            float4 f0 = make_float4(0.f, 0.f, 0.f, 0.f);
            float4 f1 = f0;
            if (r < nr) {
                const float4* ep =
                    reinterpret_cast<const float4*>(&efeats[(size_t)er * 32 + qt * 8]);
                f0 = ep[0]; f1 = ep[1];
            }
            unsigned long long* es = &Esh[wid][r][qt * 8];
            es[0] = pack2(f0.x, f0.x); es[1] = pack2(f0.y, f0.y);
            es[2] = pack2(f0.z, f0.z); es[3] = pack2(f0.w, f0.w);
            es[4] = pack2(f1.x, f1.x); es[5] = pack2(f1.y, f1.y);
            es[6] = pack2(f1.z, f1.z); es[7] = pack2(f1.w, f1.w);
        }
        __syncwarp();

        ulonglong2 acc[8];
        #pragma unroll
        for (int r = 0; r < 8; ++r) { acc[r].x = 0ull; acc[r].y = 0ull; }

        #pragma unroll
        for (int k = 0; k < 32; ++k) {
            #pragma unroll
            for (int r = 0; r < 8; ++r) {
                unsigned long long a = Esh[wid][r][k];   // broadcast
                acc[r].x = fma2(a, wreg[k].x, acc[r].x);
                acc[r].y = fma2(a, wreg[k].y, acc[r].y);
            }
        }

        #pragma unroll
        for (int r = 0; r < 8; ++r) {
            if (r < nr) {
                int sn = __shfl_sync(0xffffffffu, sr, r);
                float4 uu = *reinterpret_cast<const float4*>(&u[(size_t)sn * 128 + lane * 4]);
                float2 c0 = unpack2(acc[r].x);
                float2 c1 = unpack2(acc[r].y);
                a0 += fmaxf(uu.x + c0.x, 0.f);
                a1 += fmaxf(uu.y + c0.y, 0.f);
                a2 += fmaxf(uu.z + c1.x, 0.f);
                a3 += fmaxf(uu.w + c1.y, 0.f);
            }
        }
        __syncwarp();
    }

    const float inv = g_inv[v];
    *reinterpret_cast<float4*>(&s[(size_t)v * 128 + lane * 4]) =
        make_float4(a0 * inv, a1 * inv, a2 * inv, a3 * inv);
}

// ---------------- edge predictor ----------------
__global__ void __launch_bounds__(256)
k_pred(const int* __restrict__ src, const int* __restrict__ dst,
       const float* __restrict__ p, const float* __restrict__ q,
       const float* __restrict__ W2, const float* __restrict__ b2,
       float* __restrict__ out)
{
    const int wid  = threadIdx.x >> 5;
    const int lane = threadIdx.x & 31;
    const int e    = blockIdx.x * 8 + wid;             // exact: E = 200000*8

    float2 w2[4];
    #pragma unroll
    for (int t = 0; t < 4; ++t)
        w2[t] = reinterpret_cast<const float2*>(W2)[lane * 4 + t];

    int sn = src[e];
    int dn = dst[e];
    float4 pp = *reinterpret_cast<const float4*>(&p[(size_t)sn * 128 + lane * 4]);
    float4 qq = *reinterpret_cast<const float4*>(&q[(size_t)dn * 128 + lane * 4]);
    float h0 = fmaxf(pp.x + qq.x, 0.f);
    float h1 = fmaxf(pp.y + qq.y, 0.f);
    float h2 = fmaxf(pp.z + qq.z, 0.f);
    float h3 = fmaxf(pp.w + qq.w, 0.f);
    float s0 = h0 * w2[0].x + h1 * w2[1].x + h2 * w2[2].x + h3 * w2[3].x;
    float s1 = h0 * w2[0].y + h1 * w2[1].y + h2 * w2[2].y + h3 * w2[3].y;

    #pragma unroll
    for (int off = 16; off > 0; off >>= 1) {
        s0 += __shfl_xor_sync(0xffffffffu, s0, off);
        s1 += __shfl_xor_sync(0xffffffffu, s1, off);
    }
    if (lane == 0) {
        out[2 * (size_t)e]     = s0 + b2[0];
        out[2 * (size_t)e + 1] = s1 + b2[1];
    }
}

// ---------------- launch ----------------
extern "C" void kernel_launch(void* const* d_in, const int* in_sizes, int n_in,
                              void* d_out, int out_size)
{
    const float* nfeats = (const float*)d_in[0];
    const float* efeats = (const float*)d_in[1];
    const int*   src    = (const int*)  d_in[2];
    const int*   dst    = (const int*)  d_in[3];
    const float* Wm1 = (const float*)d_in[4];  const float* bm1 = (const float*)d_in[5];
    const float* Wa1 = (const float*)d_in[6];  const float* ba1 = (const float*)d_in[7];
    const float* Wm2 = (const float*)d_in[8];  const float* bm2 = (const float*)d_in[9];
    const float* Wa2 = (const float*)d_in[10]; const float* ba2 = (const float*)d_in[11];
    const float* W1  = (const float*)d_in[12]; const float* b1  = (const float*)d_in[13];
    const float* W2  = (const float*)d_in[14]; const float* b2  = (const float*)d_in[15];
    float* out = (float*)d_out;

    float *u, *s, *h1, *h2, *p, *q;
    cudaGetSymbolAddress((void**)&u,  g_u);
    cudaGetSymbolAddress((void**)&s,  g_s);
    cudaGetSymbolAddress((void**)&h1, g_h1);
    cudaGetSymbolAddress((void**)&h2, g_h2);
    cudaGetSymbolAddress((void**)&p,  g_p);
    cudaGetSymbolAddress((void**)&q,  g_q);

    const int GB = (NNODES + 63) / 64;        // 782 gemm blocks
    const int EB = NEDGES / 256;              // 6250 edge-parallel blocks (exact)
    const int NB = (NNODES + 255) / 256;      // 196 node-parallel blocks
    const int AB = NNODES / 4;                // 12500 aggregation blocks (exact)

    // ---- CSR build (once, shared by both layers) ----
    k_zero_cnt<<<NB, 256>>>();
    k_count<<<EB, 256>>>(dst);
    k_scan1<<<NB, 256>>>();
    k_scan2<<<1, 256>>>(NB);
    k_scan3<<<NB, 256>>>();
    k_scatter<<<EB, 256>>>(src, dst);

    // ---- SAGE layer 1 ----
    k_gemm<<<GB, 256>>>(nfeats, 64, nullptr, 0, Wm1, bm1, u, 0);
    k_aggr<<<AB, 128>>>(efeats, Wm1 + 64 * 128, u, s);
    k_gemm<<<GB, 256>>>(nfeats, 64, s, 128, Wa1, ba1, h1, 1);

    // ---- SAGE layer 2 ----
    k_gemm<<<GB, 256>>>(h1, 128, nullptr, 0, Wm2, bm2, u, 0);
    k_aggr<<<AB, 128>>>(efeats, Wm2 + 128 * 128, u, s);
    k_gemm<<<GB, 256>>>(h1, 128, s, 128, Wa2, ba2, h2, 1);

    // ---- predictor ----
    k_gemm<<<GB, 256>>>(h2, 128, nullptr, 0, W1, b1, p, 0);
    k_gemm<<<GB, 256>>>(h2, 128, nullptr, 0, W1 + 128 * 128, nullptr, q, 0);
    k_pred<<<NEDGES / 8, 256>>>(src, dst, p, q, W2, b2, out);
}

// round 5
// speedup vs baseline: 1.3526x; 1.3526x over previous
#include <cuda_runtime.h>

#define NNODES 50000
#define NEDGES 1600000

// ---------------- scratch (no allocations allowed) ----------------
__device__ float g_u [NNODES * 128];
__device__ float g_s [NNODES * 128];
__device__ float g_h1[NNODES * 128];
__device__ float g_h2[NNODES * 128];
__device__ float g_p [NNODES * 128];
__device__ float g_q [NNODES * 128];
__device__ int   g_cnt[NNODES];
__device__ float g_inv[NNODES];

// ---------------- packed f32x2 helpers ----------------
__device__ __forceinline__ unsigned long long fma2(unsigned long long a,
                                                   unsigned long long b,
                                                   unsigned long long c) {
    unsigned long long d;
    asm("fma.rn.f32x2 %0, %1, %2, %3;" : "=l"(d) : "l"(a), "l"(b), "l"(c));
    return d;
}
__device__ __forceinline__ unsigned long long pack2(float x, float y) {
    unsigned long long d;
    asm("mov.b64 %0, {%1, %2};" : "=l"(d) : "f"(x), "f"(y));
    return d;
}
__device__ __forceinline__ float2 unpack2(unsigned long long v) {
    float2 r;
    asm("mov.b64 {%0, %1}, %2;" : "=f"(r.x), "=f"(r.y) : "l"(v));
    return r;
}

// ---------------- degree count ----------------
__global__ void k_zero_cnt() {
    int i = blockIdx.x * blockDim.x + threadIdx.x;
    if (i < NNODES) g_cnt[i] = 0;
}
__global__ void k_count(const int* __restrict__ dst) {
    int e = blockIdx.x * blockDim.x + threadIdx.x;          // exactly NEDGES threads
    atomicAdd(&g_cnt[dst[e]], 1);
}
__global__ void k_inv() {
    int i = blockIdx.x * blockDim.x + threadIdx.x;
    if (i < NNODES) g_inv[i] = 1.0f / fmaxf((float)g_cnt[i], 1.0f);
}
__global__ void k_zero_f4(float* __restrict__ ptr) {
    int i = blockIdx.x * blockDim.x + threadIdx.x;          // exactly N*128/4 threads
    reinterpret_cast<float4*>(ptr)[i] = make_float4(0.f, 0.f, 0.f, 0.f);
}

// ---------------- node GEMM: C = act( [A1 | A2*rowscale] @ W + bias ) -------
// W row-major [(K1+K2) x 128]. 64-node x 128-col tile, 256 threads,
// thread tile = 4 nodes x 8 cols (4 packed f32x2 pairs).
__global__ void __launch_bounds__(256)
k_gemm(const float* __restrict__ A1, int K1,
       const float* __restrict__ A2, int K2, int scaleA2,
       const float* __restrict__ W, const float* __restrict__ bias,
       float* __restrict__ C, int doRelu)
{
    __shared__ float Ash[32][65];
    __shared__ unsigned long long Wshp[32][64];

    const int tid  = threadIdx.x;
    const int cg   = tid & 15;
    const int rg   = tid >> 4;
    const int col0 = cg << 3;
    const int row0 = rg << 2;
    const int n0   = blockIdx.x * 64;
    const int Ktot = K1 + K2;

    unsigned long long acc[4][4];
    #pragma unroll
    for (int i = 0; i < 4; ++i)
        #pragma unroll
        for (int t = 0; t < 4; ++t) acc[i][t] = 0ull;

    for (int kb = 0; kb < Ktot; kb += 32) {
        #pragma unroll
        for (int l = 0; l < 8; ++l) {
            int e  = tid + l * 256;
            int nd = e >> 5, k = e & 31;
            int gn = n0 + nd, gk = kb + k;
            float v = 0.f;
            if (gn < NNODES) {
                if (gk < K1) v = A1[(size_t)gn * K1 + gk];
                else {
                    v = A2[(size_t)gn * K2 + (gk - K1)];
                    if (scaleA2) v *= g_inv[gn];
                }
            }
            Ash[k][nd] = v;
        }
        #pragma unroll
        for (int l = 0; l < 8; ++l) {
            int e = tid + l * 256;
            int k = e >> 6, cp = e & 63;
            Wshp[k][cp] =
                reinterpret_cast<const unsigned long long*>(W + (size_t)(kb + k) * 128)[cp];
        }
        __syncthreads();

        #pragma unroll
        for (int k = 0; k < 32; ++k) {
            float a0 = Ash[k][row0 + 0];
            float a1 = Ash[k][row0 + 1];
            float a2 = Ash[k][row0 + 2];
            float a3 = Ash[k][row0 + 3];
            unsigned long long p0 = pack2(a0, a0);
            unsigned long long p1 = pack2(a1, a1);
            unsigned long long p2 = pack2(a2, a2);
            unsigned long long p3 = pack2(a3, a3);
            ulonglong2 w0 = *reinterpret_cast<const ulonglong2*>(&Wshp[k][cg * 4]);
            ulonglong2 w1 = *reinterpret_cast<const ulonglong2*>(&Wshp[k][cg * 4 + 2]);
            acc[0][0] = fma2(p0, w0.x, acc[0][0]); acc[0][1] = fma2(p0, w0.y, acc[0][1]);
            acc[0][2] = fma2(p0, w1.x, acc[0][2]); acc[0][3] = fma2(p0, w1.y, acc[0][3]);
            acc[1][0] = fma2(p1, w0.x, acc[1][0]); acc[1][1] = fma2(p1, w0.y, acc[1][1]);
            acc[1][2] = fma2(p1, w1.x, acc[1][2]); acc[1][3] = fma2(p1, w1.y, acc[1][3]);
            acc[2][0] = fma2(p2, w0.x, acc[2][0]); acc[2][1] = fma2(p2, w0.y, acc[2][1]);
            acc[2][2] = fma2(p2, w1.x, acc[2][2]); acc[2][3] = fma2(p2, w1.y, acc[2][3]);
            acc[3][0] = fma2(p3, w0.x, acc[3][0]); acc[3][1] = fma2(p3, w0.y, acc[3][1]);
            acc[3][2] = fma2(p3, w1.x, acc[3][2]); acc[3][3] = fma2(p3, w1.y, acc[3][3]);
        }
        __syncthreads();
    }

    float bv[8];
    #pragma unroll
    for (int t = 0; t < 8; ++t) bv[t] = bias ? bias[col0 + t] : 0.f;

    #pragma unroll
    for (int i = 0; i < 4; ++i) {
        int gn = n0 + row0 + i;
        if (gn >= NNODES) continue;
        float2 v0 = unpack2(acc[i][0]);
        float2 v1 = unpack2(acc[i][1]);
        float2 v2 = unpack2(acc[i][2]);
        float2 v3 = unpack2(acc[i][3]);
        float o[8] = { v0.x + bv[0], v0.y + bv[1], v1.x + bv[2], v1.y + bv[3],
                       v2.x + bv[4], v2.y + bv[5], v3.x + bv[6], v3.y + bv[7] };
        if (doRelu) {
            #pragma unroll
            for (int t = 0; t < 8; ++t) o[t] = fmaxf(o[t], 0.f);
        }
        float* cp = &C[(size_t)gn * 128 + col0];
        *reinterpret_cast<float4*>(cp)     = make_float4(o[0], o[1], o[2], o[3]);
        *reinterpret_cast<float4*>(cp + 4) = make_float4(o[4], o[5], o[6], o[7]);
    }
}

// ---------------- dense edge GEMM + fused aggregate epilogue ----------------
// Tile: 64 edges x 128 cols, K=32 (single K block). Same inner loop as k_gemm
// (fma-bound, weights amortized over 64 rows). Epilogue: per edge row
// m = relu(u[src] + c), red.global.add.v4 into s[dst]. Mean applied later.
__global__ void __launch_bounds__(256)
k_edge(const float* __restrict__ efeats, const int* __restrict__ src,
       const int* __restrict__ dst, const float* __restrict__ We,
       const float* __restrict__ u, float* __restrict__ s)
{
    __shared__ float Ash[32][65];                    // efeats tile, transposed
    __shared__ unsigned long long Wshp[32][64];      // We as f32x2 pairs

    const int tid  = threadIdx.x;
    const int cg   = tid & 15;
    const int rg   = tid >> 4;
    const int col0 = cg << 3;
    const int row0 = rg << 2;
    const int e0   = blockIdx.x * 64;                // exact: E = 25000*64

    // stage A: 64 edges x 32 feats, coalesced float4 then transpose into smem
    #pragma unroll
    for (int l = 0; l < 2; ++l) {
        int i  = tid + l * 256;                      // float4 index in [0,512)
        int nd = i >> 3;                             // edge row 0..63
        int q  = i & 7;                              // float4 within row
        float4 f = reinterpret_cast<const float4*>(efeats)[(size_t)(e0 + nd) * 8 + q];
        int k = q * 4;
        Ash[k + 0][nd] = f.x;
        Ash[k + 1][nd] = f.y;
        Ash[k + 2][nd] = f.z;
        Ash[k + 3][nd] = f.w;
    }
    // stage W: 32 x 128 as 2048 u64
    #pragma unroll
    for (int l = 0; l < 8; ++l) {
        int e = tid + l * 256;
        int k = e >> 6, cp = e & 63;
        Wshp[k][cp] =
            reinterpret_cast<const unsigned long long*>(We + (size_t)k * 128)[cp];
    }
    __syncthreads();

    unsigned long long acc[4][4];
    #pragma unroll
    for (int i = 0; i < 4; ++i)
        #pragma unroll
        for (int t = 0; t < 4; ++t) acc[i][t] = 0ull;

    #pragma unroll
    for (int k = 0; k < 32; ++k) {
        float a0 = Ash[k][row0 + 0];
        float a1 = Ash[k][row0 + 1];
        float a2 = Ash[k][row0 + 2];
        float a3 = Ash[k][row0 + 3];
        unsigned long long p0 = pack2(a0, a0);
        unsigned long long p1 = pack2(a1, a1);
        unsigned long long p2 = pack2(a2, a2);
        unsigned long long p3 = pack2(a3, a3);
        ulonglong2 w0 = *reinterpret_cast<const ulonglong2*>(&Wshp[k][cg * 4]);
        ulonglong2 w1 = *reinterpret_cast<const ulonglong2*>(&Wshp[k][cg * 4 + 2]);
        acc[0][0] = fma2(p0, w0.x, acc[0][0]); acc[0][1] = fma2(p0, w0.y, acc[0][1]);
        acc[0][2] = fma2(p0, w1.x, acc[0][2]); acc[0][3] = fma2(p0, w1.y, acc[0][3]);
        acc[1][0] = fma2(p1, w0.x, acc[1][0]); acc[1][1] = fma2(p1, w0.y, acc[1][1]);
        acc[1][2] = fma2(p1, w1.x, acc[1][2]); acc[1][3] = fma2(p1, w1.y, acc[1][3]);
        acc[2][0] = fma2(p2, w0.x, acc[2][0]); acc[2][1] = fma2(p2, w0.y, acc[2][1]);
        acc[2][2] = fma2(p2, w1.x, acc[2][2]); acc[2][3] = fma2(p2, w1.y, acc[2][3]);
        acc[3][0] = fma2(p3, w0.x, acc[3][0]); acc[3][1] = fma2(p3, w0.y, acc[3][1]);
        acc[3][2] = fma2(p3, w1.x, acc[3][2]); acc[3][3] = fma2(p3, w1.y, acc[3][3]);
    }

    // epilogue: m = relu(u[src] + c); red-add into s[dst]
    #pragma unroll
    for (int i = 0; i < 4; ++i) {
        int e  = e0 + row0 + i;
        int sn = __ldg(&src[e]);
        int dn = __ldg(&dst[e]);
        const float* up = &u[(size_t)sn * 128 + col0];
        float4 u0 = *reinterpret_cast<const float4*>(up);
        float4 u1 = *reinterpret_cast<const float4*>(up + 4);
        float2 v0 = unpack2(acc[i][0]);
        float2 v1 = unpack2(acc[i][1]);
        float2 v2 = unpack2(acc[i][2]);
        float2 v3 = unpack2(acc[i][3]);
        float m0 = fmaxf(u0.x + v0.x, 0.f);
        float m1 = fmaxf(u0.y + v0.y, 0.f);
        float m2 = fmaxf(u0.z + v1.x, 0.f);
        float m3 = fmaxf(u0.w + v1.y, 0.f);
        float m4 = fmaxf(u1.x + v2.x, 0.f);
        float m5 = fmaxf(u1.y + v2.y, 0.f);
        float m6 = fmaxf(u1.z + v3.x, 0.f);
        float m7 = fmaxf(u1.w + v3.y, 0.f);
        float* sp = &s[(size_t)dn * 128 + col0];
        asm volatile("red.global.add.v4.f32 [%0], {%1, %2, %3, %4};"
                     :: "l"(sp), "f"(m0), "f"(m1), "f"(m2), "f"(m3) : "memory");
        asm volatile("red.global.add.v4.f32 [%0], {%1, %2, %3, %4};"
                     :: "l"(sp + 4), "f"(m4), "f"(m5), "f"(m6), "f"(m7) : "memory");
    }
}

// ---------------- edge predictor ----------------
__global__ void __launch_bounds__(256)
k_pred(const int* __restrict__ src, const int* __restrict__ dst,
       const float* __restrict__ p, const float* __restrict__ q,
       const float* __restrict__ W2, const float* __restrict__ b2,
       float* __restrict__ out)
{
    const int wid  = threadIdx.x >> 5;
    const int lane = threadIdx.x & 31;
    const int e    = blockIdx.x * 8 + wid;             // exact: E = 200000*8

    float2 w2[4];
    #pragma unroll
    for (int t = 0; t < 4; ++t)
        w2[t] = reinterpret_cast<const float2*>(W2)[lane * 4 + t];

    int sn = src[e];
    int dn = dst[e];
    float4 pp = *reinterpret_cast<const float4*>(&p[(size_t)sn * 128 + lane * 4]);
    float4 qq = *reinterpret_cast<const float4*>(&q[(size_t)dn * 128 + lane * 4]);
    float h0 = fmaxf(pp.x + qq.x, 0.f);
    float h1 = fmaxf(pp.y + qq.y, 0.f);
    float h2 = fmaxf(pp.z + qq.z, 0.f);
    float h3 = fmaxf(pp.w + qq.w, 0.f);
    float s0 = h0 * w2[0].x + h1 * w2[1].x + h2 * w2[2].x + h3 * w2[3].x;
    float s1 = h0 * w2[0].y + h1 * w2[1].y + h2 * w2[2].y + h3 * w2[3].y;

    #pragma unroll
    for (int off = 16; off > 0; off >>= 1) {
        s0 += __shfl_xor_sync(0xffffffffu, s0, off);
        s1 += __shfl_xor_sync(0xffffffffu, s1, off);
    }
    if (lane == 0) {
        out[2 * (size_t)e]     = s0 + b2[0];
        out[2 * (size_t)e + 1] = s1 + b2[1];
    }
}

// ---------------- launch ----------------
extern "C" void kernel_launch(void* const* d_in, const int* in_sizes, int n_in,
                              void* d_out, int out_size)
{
    const float* nfeats = (const float*)d_in[0];
    const float* efeats = (const float*)d_in[1];
    const int*   src    = (const int*)  d_in[2];
    const int*   dst    = (const int*)  d_in[3];
    const float* Wm1 = (const float*)d_in[4];  const float* bm1 = (const float*)d_in[5];
    const float* Wa1 = (const float*)d_in[6];  const float* ba1 = (const float*)d_in[7];
    const float* Wm2 = (const float*)d_in[8];  const float* bm2 = (const float*)d_in[9];
    const float* Wa2 = (const float*)d_in[10]; const float* ba2 = (const float*)d_in[11];
    const float* W1  = (const float*)d_in[12]; const float* b1  = (const float*)d_in[13];
    const float* W2  = (const float*)d_in[14]; const float* b2  = (const float*)d_in[15];
    float* out = (float*)d_out;

    float *u, *s, *h1, *h2, *p, *q;
    cudaGetSymbolAddress((void**)&u,  g_u);
    cudaGetSymbolAddress((void**)&s,  g_s);
    cudaGetSymbolAddress((void**)&h1, g_h1);
    cudaGetSymbolAddress((void**)&h2, g_h2);
    cudaGetSymbolAddress((void**)&p,  g_p);
    cudaGetSymbolAddress((void**)&q,  g_q);

    const int GB = (NNODES + 63) / 64;        // 782 gemm blocks
    const int ZB = NNODES * 128 / 4 / 256;    // 6250 zero blocks (exact)
    const int EB = NEDGES / 64;               // 25000 edge-gemm blocks (exact)
    const int CB = NEDGES / 256;              // 6250 count blocks (exact)
    const int NB = (NNODES + 255) / 256;      // 196

    // degree counts (once)
    k_zero_cnt<<<NB, 256>>>();
    k_count<<<CB, 256>>>(dst);
    k_inv<<<NB, 256>>>();

    // ---- SAGE layer 1 ----
    k_zero_f4<<<ZB, 256>>>(s);
    k_gemm<<<GB, 256>>>(nfeats, 64, nullptr, 0, 0, Wm1, bm1, u, 0);
    k_edge<<<EB, 256>>>(efeats, src, dst, Wm1 + 64 * 128, u, s);
    k_gemm<<<GB, 256>>>(nfeats, 64, s, 128, 1, Wa1, ba1, h1, 1);

    // ---- SAGE layer 2 ----
    k_zero_f4<<<ZB, 256>>>(s);
    k_gemm<<<GB, 256>>>(h1, 128, nullptr, 0, 0, Wm2, bm2, u, 0);
    k_edge<<<EB, 256>>>(efeats, src, dst, Wm2 + 128 * 128, u, s);
    k_gemm<<<GB, 256>>>(h1, 128, s, 128, 1, Wa2, ba2, h2, 1);

    // ---- predictor ----
    k_gemm<<<GB, 256>>>(h2, 128, nullptr, 0, 0, W1, b1, p, 0);
    k_gemm<<<GB, 256>>>(h2, 128, nullptr, 0, 0, W1 + 128 * 128, nullptr, q, 0);
    k_pred<<<NEDGES / 8, 256>>>(src, dst, p, q, W2, b2, out);
}

// round 6
// speedup vs baseline: 1.9526x; 1.4436x over previous
#include <cuda_runtime.h>

#define NNODES 50000
#define NEDGES 1600000

// ---------------- scratch (no allocations allowed) ----------------
__device__ float g_u [NNODES * 128];
__device__ float g_s [NNODES * 128];
__device__ float g_h1[NNODES * 128];
__device__ float g_h2[NNODES * 128];
__device__ float g_p [NNODES * 128];
__device__ float g_q [NNODES * 128];
__device__ int   g_cnt[NNODES];
__device__ float g_inv[NNODES];

// ---------------- packed f32x2 helpers ----------------
__device__ __forceinline__ unsigned long long fma2(unsigned long long a,
                                                   unsigned long long b,
                                                   unsigned long long c) {
    unsigned long long d;
    asm("fma.rn.f32x2 %0, %1, %2, %3;" : "=l"(d) : "l"(a), "l"(b), "l"(c));
    return d;
}
__device__ __forceinline__ unsigned long long pack2(float x, float y) {
    unsigned long long d;
    asm("mov.b64 %0, {%1, %2};" : "=l"(d) : "f"(x), "f"(y));
    return d;
}
__device__ __forceinline__ float2 unpack2(unsigned long long v) {
    float2 r;
    asm("mov.b64 {%0, %1}, %2;" : "=f"(r.x), "=f"(r.y) : "l"(v));
    return r;
}

// ---------------- tiny utility kernels ----------------
__global__ void k_zero_cnt() {
    int i = blockIdx.x * blockDim.x + threadIdx.x;
    if (i < NNODES) g_cnt[i] = 0;
}
__global__ void k_count(const int* __restrict__ dst) {
    int e = blockIdx.x * blockDim.x + threadIdx.x;          // exactly NEDGES threads
    atomicAdd(&g_cnt[dst[e]], 1);
}
__global__ void k_inv() {
    int i = blockIdx.x * blockDim.x + threadIdx.x;
    if (i < NNODES) g_inv[i] = 1.0f / fmaxf((float)g_cnt[i], 1.0f);
}
__global__ void k_zero_f4(float* __restrict__ ptr) {
    int i = blockIdx.x * blockDim.x + threadIdx.x;          // exactly N*128/4 threads
    reinterpret_cast<float4*>(ptr)[i] = make_float4(0.f, 0.f, 0.f, 0.f);
}

// ---------------- node GEMM: C = act( [A1 | A2*rowscale] @ W + bias ) -------
// W row-major [(K1+K2) x 128]. 128-row x 128-col tile, 256 threads,
// thread tile = 8 rows x 8 cols. Ash stored [k][row] so A reads are LDS.128.
__global__ void __launch_bounds__(256, 2)
k_gemm(const float* __restrict__ A1, int K1,
       const float* __restrict__ A2, int K2, int scaleA2,
       const float* __restrict__ W, const float* __restrict__ bias,
       float* __restrict__ C, int doRelu)
{
    __shared__ float Ash[32][132];                   // [k][row], 528B stride (16B-aligned)
    __shared__ unsigned long long Wshp[32][64];      // W as f32x2 pairs

    const int tid  = threadIdx.x;
    const int cg   = tid & 15;          // col group -> cols [8cg, 8cg+8)
    const int rg   = tid >> 4;          // row group -> rows [8rg, 8rg+8)
    const int col0 = cg << 3;
    const int row0 = rg << 3;
    const int n0   = blockIdx.x * 128;
    const int Ktot = K1 + K2;

    unsigned long long acc[8][4];
    #pragma unroll
    for (int i = 0; i < 8; ++i)
        #pragma unroll
        for (int t = 0; t < 4; ++t) acc[i][t] = 0ull;

    for (int kb = 0; kb < Ktot; kb += 32) {
        // stage A: 128 rows x 32 k, as float4, stored transposed [k][row]
        #pragma unroll
        for (int l = 0; l < 4; ++l) {
            int i   = tid + l * 256;                 // 0..1023
            int row = i >> 3;                        // 0..127
            int q   = i & 7;                         // float4 within k-block
            int gn  = n0 + row;
            int gk  = kb + q * 4;
            float4 f = make_float4(0.f, 0.f, 0.f, 0.f);
            if (gn < NNODES) {
                if (gk < K1) f = *reinterpret_cast<const float4*>(&A1[(size_t)gn * K1 + gk]);
                else {
                    f = *reinterpret_cast<const float4*>(&A2[(size_t)gn * K2 + (gk - K1)]);
                    if (scaleA2) {
                        float iv = g_inv[gn];
                        f.x *= iv; f.y *= iv; f.z *= iv; f.w *= iv;
                    }
                }
            }
            int kk = q * 4;
            Ash[kk + 0][row] = f.x;
            Ash[kk + 1][row] = f.y;
            Ash[kk + 2][row] = f.z;
            Ash[kk + 3][row] = f.w;
        }
        // stage W: 32 x 128 as 2048 u64
        #pragma unroll
        for (int l = 0; l < 8; ++l) {
            int e = tid + l * 256;
            int k = e >> 6, cp = e & 63;
            Wshp[k][cp] =
                reinterpret_cast<const unsigned long long*>(W + (size_t)(kb + k) * 128)[cp];
        }
        __syncthreads();

        #pragma unroll 8
        for (int k = 0; k < 32; ++k) {
            float4 aA = *reinterpret_cast<const float4*>(&Ash[k][row0]);
            float4 aB = *reinterpret_cast<const float4*>(&Ash[k][row0 + 4]);
            ulonglong2 w0 = *reinterpret_cast<const ulonglong2*>(&Wshp[k][cg * 4]);
            ulonglong2 w1 = *reinterpret_cast<const ulonglong2*>(&Wshp[k][cg * 4 + 2]);
            unsigned long long pr[8];
            pr[0] = pack2(aA.x, aA.x); pr[1] = pack2(aA.y, aA.y);
            pr[2] = pack2(aA.z, aA.z); pr[3] = pack2(aA.w, aA.w);
            pr[4] = pack2(aB.x, aB.x); pr[5] = pack2(aB.y, aB.y);
            pr[6] = pack2(aB.z, aB.z); pr[7] = pack2(aB.w, aB.w);
            #pragma unroll
            for (int r = 0; r < 8; ++r) {
                acc[r][0] = fma2(pr[r], w0.x, acc[r][0]);
                acc[r][1] = fma2(pr[r], w0.y, acc[r][1]);
                acc[r][2] = fma2(pr[r], w1.x, acc[r][2]);
                acc[r][3] = fma2(pr[r], w1.y, acc[r][3]);
            }
        }
        __syncthreads();
    }

    float bv[8];
    #pragma unroll
    for (int t = 0; t < 8; ++t) bv[t] = bias ? bias[col0 + t] : 0.f;

    #pragma unroll
    for (int i = 0; i < 8; ++i) {
        int gn = n0 + row0 + i;
        if (gn >= NNODES) continue;
        float2 v0 = unpack2(acc[i][0]);
        float2 v1 = unpack2(acc[i][1]);
        float2 v2 = unpack2(acc[i][2]);
        float2 v3 = unpack2(acc[i][3]);
        float o[8] = { v0.x + bv[0], v0.y + bv[1], v1.x + bv[2], v1.y + bv[3],
                       v2.x + bv[4], v2.y + bv[5], v3.x + bv[6], v3.y + bv[7] };
        if (doRelu) {
            #pragma unroll
            for (int t = 0; t < 8; ++t) o[t] = fmaxf(o[t], 0.f);
        }
        float* cp = &C[(size_t)gn * 128 + col0];
        *reinterpret_cast<float4*>(cp)     = make_float4(o[0], o[1], o[2], o[3]);
        *reinterpret_cast<float4*>(cp + 4) = make_float4(o[4], o[5], o[6], o[7]);
    }
}

// ---------------- dense edge GEMM + fused aggregate epilogue ----------------
// Tile: 128 edges x 128 cols, K=32. Epilogue: m = relu(u[src] + c),
// red.global.add.v4 into s[dst]. Mean applied by apply-GEMM via g_inv.
__global__ void __launch_bounds__(256, 2)
k_edge(const float* __restrict__ efeats, const int* __restrict__ src,
       const int* __restrict__ dst, const float* __restrict__ We,
       const float* __restrict__ u, float* __restrict__ s)
{
    __shared__ float Ash[32][132];
    __shared__ unsigned long long Wshp[32][64];

    const int tid  = threadIdx.x;
    const int cg   = tid & 15;
    const int rg   = tid >> 4;
    const int col0 = cg << 3;
    const int row0 = rg << 3;
    const int e0   = blockIdx.x * 128;               // exact: E = 12500*128

    // stage efeats: 128 edges x 32 feats
    #pragma unroll
    for (int l = 0; l < 4; ++l) {
        int i   = tid + l * 256;
        int row = i >> 3;
        int q   = i & 7;
        float4 f = reinterpret_cast<const float4*>(efeats)[(size_t)(e0 + row) * 8 + q];
        int kk = q * 4;
        Ash[kk + 0][row] = f.x;
        Ash[kk + 1][row] = f.y;
        Ash[kk + 2][row] = f.z;
        Ash[kk + 3][row] = f.w;
    }
    #pragma unroll
    for (int l = 0; l < 8; ++l) {
        int e = tid + l * 256;
        int k = e >> 6, cp = e & 63;
        Wshp[k][cp] =
            reinterpret_cast<const unsigned long long*>(We + (size_t)k * 128)[cp];
    }
    __syncthreads();

    unsigned long long acc[8][4];
    #pragma unroll
    for (int i = 0; i < 8; ++i)
        #pragma unroll
        for (int t = 0; t < 4; ++t) acc[i][t] = 0ull;

    #pragma unroll 8
    for (int k = 0; k < 32; ++k) {
        float4 aA = *reinterpret_cast<const float4*>(&Ash[k][row0]);
        float4 aB = *reinterpret_cast<const float4*>(&Ash[k][row0 + 4]);
        ulonglong2 w0 = *reinterpret_cast<const ulonglong2*>(&Wshp[k][cg * 4]);
        ulonglong2 w1 = *reinterpret_cast<const ulonglong2*>(&Wshp[k][cg * 4 + 2]);
        unsigned long long pr[8];
        pr[0] = pack2(aA.x, aA.x); pr[1] = pack2(aA.y, aA.y);
        pr[2] = pack2(aA.z, aA.z); pr[3] = pack2(aA.w, aA.w);
        pr[4] = pack2(aB.x, aB.x); pr[5] = pack2(aB.y, aB.y);
        pr[6] = pack2(aB.z, aB.z); pr[7] = pack2(aB.w, aB.w);
        #pragma unroll
        for (int r = 0; r < 8; ++r) {
            acc[r][0] = fma2(pr[r], w0.x, acc[r][0]);
            acc[r][1] = fma2(pr[r], w0.y, acc[r][1]);
            acc[r][2] = fma2(pr[r], w1.x, acc[r][2]);
            acc[r][3] = fma2(pr[r], w1.y, acc[r][3]);
        }
    }

    // epilogue: m = relu(u[src] + c); red-add into s[dst]
    #pragma unroll
    for (int i = 0; i < 8; ++i) {
        int e  = e0 + row0 + i;
        int sn = __ldg(&src[e]);
        int dn = __ldg(&dst[e]);
        const float* up = &u[(size_t)sn * 128 + col0];
        float4 u0 = *reinterpret_cast<const float4*>(up);
        float4 u1 = *reinterpret_cast<const float4*>(up + 4);
        float2 v0 = unpack2(acc[i][0]);
        float2 v1 = unpack2(acc[i][1]);
        float2 v2 = unpack2(acc[i][2]);
        float2 v3 = unpack2(acc[i][3]);
        float m0 = fmaxf(u0.x + v0.x, 0.f);
        float m1 = fmaxf(u0.y + v0.y, 0.f);
        float m2 = fmaxf(u0.z + v1.x, 0.f);
        float m3 = fmaxf(u0.w + v1.y, 0.f);
        float m4 = fmaxf(u1.x + v2.x, 0.f);
        float m5 = fmaxf(u1.y + v2.y, 0.f);
        float m6 = fmaxf(u1.z + v3.x, 0.f);
        float m7 = fmaxf(u1.w + v3.y, 0.f);
        float* sp = &s[(size_t)dn * 128 + col0];
        asm volatile("red.global.add.v4.f32 [%0], {%1, %2, %3, %4};"
                     :: "l"(sp), "f"(m0), "f"(m1), "f"(m2), "f"(m3) : "memory");
        asm volatile("red.global.add.v4.f32 [%0], {%1, %2, %3, %4};"
                     :: "l"(sp + 4), "f"(m4), "f"(m5), "f"(m6), "f"(m7) : "memory");
    }
}

// ---------------- edge predictor ----------------
__global__ void __launch_bounds__(256)
k_pred(const int* __restrict__ src, const int* __restrict__ dst,
       const float* __restrict__ p, const float* __restrict__ q,
       const float* __restrict__ W2, const float* __restrict__ b2,
       float* __restrict__ out)
{
    const int wid  = threadIdx.x >> 5;
    const int lane = threadIdx.x & 31;
    const int e    = blockIdx.x * 8 + wid;             // exact: E = 200000*8

    float2 w2[4];
    #pragma unroll
    for (int t = 0; t < 4; ++t)
        w2[t] = reinterpret_cast<const float2*>(W2)[lane * 4 + t];

    int sn = src[e];
    int dn = dst[e];
    float4 pp = *reinterpret_cast<const float4*>(&p[(size_t)sn * 128 + lane * 4]);
    float4 qq = *reinterpret_cast<const float4*>(&q[(size_t)dn * 128 + lane * 4]);
    float h0 = fmaxf(pp.x + qq.x, 0.f);
    float h1 = fmaxf(pp.y + qq.y, 0.f);
    float h2 = fmaxf(pp.z + qq.z, 0.f);
    float h3 = fmaxf(pp.w + qq.w, 0.f);
    float s0 = h0 * w2[0].x + h1 * w2[1].x + h2 * w2[2].x + h3 * w2[3].x;
    float s1 = h0 * w2[0].y + h1 * w2[1].y + h2 * w2[2].y + h3 * w2[3].y;

    #pragma unroll
    for (int off = 16; off > 0; off >>= 1) {
        s0 += __shfl_xor_sync(0xffffffffu, s0, off);
        s1 += __shfl_xor_sync(0xffffffffu, s1, off);
    }
    if (lane == 0) {
        out[2 * (size_t)e]     = s0 + b2[0];
        out[2 * (size_t)e + 1] = s1 + b2[1];
    }
}

// ---------------- launch ----------------
extern "C" void kernel_launch(void* const* d_in, const int* in_sizes, int n_in,
                              void* d_out, int out_size)
{
    const float* nfeats = (const float*)d_in[0];
    const float* efeats = (const float*)d_in[1];
    const int*   src    = (const int*)  d_in[2];
    const int*   dst    = (const int*)  d_in[3];
    const float* Wm1 = (const float*)d_in[4];  const float* bm1 = (const float*)d_in[5];
    const float* Wa1 = (const float*)d_in[6];  const float* ba1 = (const float*)d_in[7];
    const float* Wm2 = (const float*)d_in[8];  const float* bm2 = (const float*)d_in[9];
    const float* Wa2 = (const float*)d_in[10]; const float* ba2 = (const float*)d_in[11];
    const float* W1  = (const float*)d_in[12]; const float* b1  = (const float*)d_in[13];
    const float* W2  = (const float*)d_in[14]; const float* b2  = (const float*)d_in[15];
    float* out = (float*)d_out;

    float *u, *s, *h1, *h2, *p, *q;
    cudaGetSymbolAddress((void**)&u,  g_u);
    cudaGetSymbolAddress((void**)&s,  g_s);
    cudaGetSymbolAddress((void**)&h1, g_h1);
    cudaGetSymbolAddress((void**)&h2, g_h2);
    cudaGetSymbolAddress((void**)&p,  g_p);
    cudaGetSymbolAddress((void**)&q,  g_q);

    const int GB = (NNODES + 127) / 128;      // 391 gemm blocks
    const int ZB = NNODES * 128 / 4 / 256;    // 6250 zero blocks (exact)
    const int EB = NEDGES / 128;              // 12500 edge-gemm blocks (exact)
    const int CB = NEDGES / 256;              // 6250 count blocks (exact)
    const int NB = (NNODES + 255) / 256;      // 196

    // Order chosen so k_edge is the 4th launch (ncu capture index 3).
    k_zero_f4<<<ZB, 256>>>(s);                                        // 0
    k_gemm<<<GB, 256>>>(nfeats, 64, nullptr, 0, 0, Wm1, bm1, u, 0);   // 1
    k_zero_cnt<<<NB, 256>>>();                                        // 2
    k_edge<<<EB, 256>>>(efeats, src, dst, Wm1 + 64 * 128, u, s);      // 3 (captured)
    k_count<<<CB, 256>>>(dst);                                        // 4
    k_inv<<<NB, 256>>>();                                             // 5
    k_gemm<<<GB, 256>>>(nfeats, 64, s, 128, 1, Wa1, ba1, h1, 1);      // 6

    // ---- SAGE layer 2 ----
    k_zero_f4<<<ZB, 256>>>(s);
    k_gemm<<<GB, 256>>>(h1, 128, nullptr, 0, 0, Wm2, bm2, u, 0);
    k_edge<<<EB, 256>>>(efeats, src, dst, Wm2 + 128 * 128, u, s);
    k_gemm<<<GB, 256>>>(h1, 128, s, 128, 1, Wa2, ba2, h2, 1);

    // ---- predictor ----
    k_gemm<<<GB, 256>>>(h2, 128, nullptr, 0, 0, W1, b1, p, 0);
    k_gemm<<<GB, 256>>>(h2, 128, nullptr, 0, 0, W1 + 128 * 128, nullptr, q, 0);
    k_pred<<<NEDGES / 8, 256>>>(src, dst, p, q, W2, b2, out);
}

// round 7
// speedup vs baseline: 2.3014x; 1.1786x over previous
#include <cuda_runtime.h>

#define NNODES 50000
#define NEDGES 1600000

// ---------------- scratch (no allocations allowed) ----------------
__device__ float g_u [NNODES * 128];
__device__ float g_s [NNODES * 128];
__device__ float g_h1[NNODES * 128];
__device__ float g_h2[NNODES * 128];
__device__ float g_p [NNODES * 128];
__device__ float g_q [NNODES * 128];
__device__ int   g_cnt[NNODES];
__device__ float g_inv[NNODES];

// ---------------- packed f32x2 helpers ----------------
__device__ __forceinline__ unsigned long long fma2(unsigned long long a,
                                                   unsigned long long b,
                                                   unsigned long long c) {
    unsigned long long d;
    asm("fma.rn.f32x2 %0, %1, %2, %3;" : "=l"(d) : "l"(a), "l"(b), "l"(c));
    return d;
}
__device__ __forceinline__ unsigned long long pack2(float x, float y) {
    unsigned long long d;
    asm("mov.b64 %0, {%1, %2};" : "=l"(d) : "f"(x), "f"(y));
    return d;
}
__device__ __forceinline__ float2 unpack2(unsigned long long v) {
    float2 r;
    asm("mov.b64 {%0, %1}, %2;" : "=f"(r.x), "=f"(r.y) : "l"(v));
    return r;
}

// ---------------- tiny utility kernels ----------------
__global__ void k_zero_cnt() {
    int i = blockIdx.x * blockDim.x + threadIdx.x;
    if (i < NNODES) g_cnt[i] = 0;
}
__global__ void k_count(const int* __restrict__ dst) {
    int e = blockIdx.x * blockDim.x + threadIdx.x;          // exactly NEDGES threads
    atomicAdd(&g_cnt[dst[e]], 1);
}
__global__ void k_inv() {
    int i = blockIdx.x * blockDim.x + threadIdx.x;
    if (i < NNODES) g_inv[i] = 1.0f / fmaxf((float)g_cnt[i], 1.0f);
}
__global__ void k_zero_f4(float* __restrict__ ptr) {
    int i = blockIdx.x * blockDim.x + threadIdx.x;          // exactly N*128/4 threads
    reinterpret_cast<float4*>(ptr)[i] = make_float4(0.f, 0.f, 0.f, 0.f);
}

// ---------------- node GEMM: C = act( [A1 | A2*rowscale] @ W + bias ) -------
// 128-row x 128-col tile, 256 threads. lane -> 4 cols, warp -> 16 rows.
// Rows packed in f32x2 pairs; A reads are warp-uniform broadcasts (1 wf),
// W read is one LDS.128 per k (4 wf). 8 wf per 32 fma2.
__global__ void __launch_bounds__(256, 2)
k_gemm(const float* __restrict__ A1, int K1,
       const float* __restrict__ A2, int K2, int scaleA2,
       const float* __restrict__ W, const float* __restrict__ bias,
       float* __restrict__ C, int doRelu)
{
    __shared__ float Ash[32][132];                   // [k][row]
    __shared__ float Wsh[32][132];                   // [k][col]

    const int tid  = threadIdx.x;
    const int lane = tid & 31;
    const int wp   = tid >> 5;
    const int col0 = lane << 2;                      // 4 cols per lane
    const int row0 = wp << 4;                        // 16 rows per warp
    const int n0   = blockIdx.x * 128;
    const int Ktot = K1 + K2;

    unsigned long long acc[8][4];                    // [rowpair][col]
    #pragma unroll
    for (int i = 0; i < 8; ++i)
        #pragma unroll
        for (int t = 0; t < 4; ++t) acc[i][t] = 0ull;

    for (int kb = 0; kb < Ktot; kb += 32) {
        // stage A: 128 rows x 32 k, float4 loads, stored transposed [k][row]
        #pragma unroll
        for (int l = 0; l < 4; ++l) {
            int i   = tid + l * 256;                 // 0..1023
            int row = i >> 3;
            int q   = i & 7;
            int gn  = n0 + row;
            int gk  = kb + q * 4;
            float4 f = make_float4(0.f, 0.f, 0.f, 0.f);
            if (gn < NNODES) {
                if (gk < K1) f = *reinterpret_cast<const float4*>(&A1[(size_t)gn * K1 + gk]);
                else {
                    f = *reinterpret_cast<const float4*>(&A2[(size_t)gn * K2 + (gk - K1)]);
                    if (scaleA2) {
                        float iv = g_inv[gn];
                        f.x *= iv; f.y *= iv; f.z *= iv; f.w *= iv;
                    }
                }
            }
            int kk = q * 4;
            Ash[kk + 0][row] = f.x;
            Ash[kk + 1][row] = f.y;
            Ash[kk + 2][row] = f.z;
            Ash[kk + 3][row] = f.w;
        }
        // stage W: 32 x 128 floats via float4
        #pragma unroll
        for (int l = 0; l < 4; ++l) {
            int i = tid + l * 256;                   // 0..1023 float4s
            int k = i >> 5, q = i & 31;
            float4 f = *reinterpret_cast<const float4*>(&W[(size_t)(kb + k) * 128 + q * 4]);
            *reinterpret_cast<float4*>(&Wsh[k][q * 4]) = f;
        }
        __syncthreads();

        #pragma unroll 8
        for (int k = 0; k < 32; ++k) {
            // A: 16 rows as 4 uniform float4 loads -> 8 aligned row-pairs
            ulonglong2 a01 = *reinterpret_cast<const ulonglong2*>(&Ash[k][row0]);
            ulonglong2 a23 = *reinterpret_cast<const ulonglong2*>(&Ash[k][row0 + 4]);
            ulonglong2 a45 = *reinterpret_cast<const ulonglong2*>(&Ash[k][row0 + 8]);
            ulonglong2 a67 = *reinterpret_cast<const ulonglong2*>(&Ash[k][row0 + 12]);
            unsigned long long ap[8] = { a01.x, a01.y, a23.x, a23.y,
                                         a45.x, a45.y, a67.x, a67.y };
            // W: 4 cols, duplicated into pairs
            float4 wv = *reinterpret_cast<const float4*>(&Wsh[k][col0]);
            unsigned long long wd[4] = { pack2(wv.x, wv.x), pack2(wv.y, wv.y),
                                         pack2(wv.z, wv.z), pack2(wv.w, wv.w) };
            #pragma unroll
            for (int r = 0; r < 8; ++r) {
                acc[r][0] = fma2(ap[r], wd[0], acc[r][0]);
                acc[r][1] = fma2(ap[r], wd[1], acc[r][1]);
                acc[r][2] = fma2(ap[r], wd[2], acc[r][2]);
                acc[r][3] = fma2(ap[r], wd[3], acc[r][3]);
            }
        }
        __syncthreads();
    }

    float bv[4];
    #pragma unroll
    for (int t = 0; t < 4; ++t) bv[t] = bias ? bias[col0 + t] : 0.f;

    #pragma unroll
    for (int rp = 0; rp < 8; ++rp) {
        float2 a0 = unpack2(acc[rp][0]);
        float2 a1 = unpack2(acc[rp][1]);
        float2 a2 = unpack2(acc[rp][2]);
        float2 a3 = unpack2(acc[rp][3]);
        #pragma unroll
        for (int h = 0; h < 2; ++h) {
            int gn = n0 + row0 + rp * 2 + h;
            if (gn >= NNODES) continue;
            float o0 = (h ? a0.y : a0.x) + bv[0];
            float o1 = (h ? a1.y : a1.x) + bv[1];
            float o2 = (h ? a2.y : a2.x) + bv[2];
            float o3 = (h ? a3.y : a3.x) + bv[3];
            if (doRelu) {
                o0 = fmaxf(o0, 0.f); o1 = fmaxf(o1, 0.f);
                o2 = fmaxf(o2, 0.f); o3 = fmaxf(o3, 0.f);
            }
            *reinterpret_cast<float4*>(&C[(size_t)gn * 128 + col0]) =
                make_float4(o0, o1, o2, o3);
        }
    }
}

// ---------------- dense edge GEMM + fused aggregate epilogue ----------------
// Tile: 128 edges x 128 cols, K=32. Same lane->4cols / warp->16rows mapping.
// Epilogue: m = relu(u[src] + c), red.global.add.v4 into s[dst].
__global__ void __launch_bounds__(256, 2)
k_edge(const float* __restrict__ efeats, const int* __restrict__ src,
       const int* __restrict__ dst, const float* __restrict__ We,
       const float* __restrict__ u, float* __restrict__ s)
{
    __shared__ float Ash[32][132];
    __shared__ float Wsh[32][132];

    const int tid  = threadIdx.x;
    const int lane = tid & 31;
    const int wp   = tid >> 5;
    const int col0 = lane << 2;
    const int row0 = wp << 4;
    const int e0   = blockIdx.x * 128;               // exact: E = 12500*128

    #pragma unroll
    for (int l = 0; l < 4; ++l) {
        int i   = tid + l * 256;
        int row = i >> 3;
        int q   = i & 7;
        float4 f = reinterpret_cast<const float4*>(efeats)[(size_t)(e0 + row) * 8 + q];
        int kk = q * 4;
        Ash[kk + 0][row] = f.x;
        Ash[kk + 1][row] = f.y;
        Ash[kk + 2][row] = f.z;
        Ash[kk + 3][row] = f.w;
    }
    #pragma unroll
    for (int l = 0; l < 4; ++l) {
        int i = tid + l * 256;
        int k = i >> 5, q = i & 31;
        float4 f = *reinterpret_cast<const float4*>(&We[(size_t)k * 128 + q * 4]);
        *reinterpret_cast<float4*>(&Wsh[k][q * 4]) = f;
    }
    __syncthreads();

    unsigned long long acc[8][4];
    #pragma unroll
    for (int i = 0; i < 8; ++i)
        #pragma unroll
        for (int t = 0; t < 4; ++t) acc[i][t] = 0ull;

    #pragma unroll 8
    for (int k = 0; k < 32; ++k) {
        ulonglong2 a01 = *reinterpret_cast<const ulonglong2*>(&Ash[k][row0]);
        ulonglong2 a23 = *reinterpret_cast<const ulonglong2*>(&Ash[k][row0 + 4]);
        ulonglong2 a45 = *reinterpret_cast<const ulonglong2*>(&Ash[k][row0 + 8]);
        ulonglong2 a67 = *reinterpret_cast<const ulonglong2*>(&Ash[k][row0 + 12]);
        unsigned long long ap[8] = { a01.x, a01.y, a23.x, a23.y,
                                     a45.x, a45.y, a67.x, a67.y };
        float4 wv = *reinterpret_cast<const float4*>(&Wsh[k][col0]);
        unsigned long long wd[4] = { pack2(wv.x, wv.x), pack2(wv.y, wv.y),
                                     pack2(wv.z, wv.z), pack2(wv.w, wv.w) };
        #pragma unroll
        for (int r = 0; r < 8; ++r) {
            acc[r][0] = fma2(ap[r], wd[0], acc[r][0]);
            acc[r][1] = fma2(ap[r], wd[1], acc[r][1]);
            acc[r][2] = fma2(ap[r], wd[2], acc[r][2]);
            acc[r][3] = fma2(ap[r], wd[3], acc[r][3]);
        }
    }

    // epilogue: per row, m = relu(u[src] + c); red-add 16B per lane into s[dst]
    #pragma unroll
    for (int rp = 0; rp < 8; ++rp) {
        float2 a0 = unpack2(acc[rp][0]);
        float2 a1 = unpack2(acc[rp][1]);
        float2 a2 = unpack2(acc[rp][2]);
        float2 a3 = unpack2(acc[rp][3]);
        #pragma unroll
        for (int h = 0; h < 2; ++h) {
            int e  = e0 + row0 + rp * 2 + h;
            int sn = __ldg(&src[e]);
            int dn = __ldg(&dst[e]);
            float4 uu = *reinterpret_cast<const float4*>(&u[(size_t)sn * 128 + col0]);
            float m0 = fmaxf(uu.x + (h ? a0.y : a0.x), 0.f);
            float m1 = fmaxf(uu.y + (h ? a1.y : a1.x), 0.f);
            float m2 = fmaxf(uu.z + (h ? a2.y : a2.x), 0.f);
            float m3 = fmaxf(uu.w + (h ? a3.y : a3.x), 0.f);
            float* sp = &s[(size_t)dn * 128 + col0];
            asm volatile("red.global.add.v4.f32 [%0], {%1, %2, %3, %4};"
                         :: "l"(sp), "f"(m0), "f"(m1), "f"(m2), "f"(m3) : "memory");
        }
    }
}

// ---------------- edge predictor ----------------
__global__ void __launch_bounds__(256)
k_pred(const int* __restrict__ src, const int* __restrict__ dst,
       const float* __restrict__ p, const float* __restrict__ q,
       const float* __restrict__ W2, const float* __restrict__ b2,
       float* __restrict__ out)
{
    const int wid  = threadIdx.x >> 5;
    const int lane = threadIdx.x & 31;
    const int e    = blockIdx.x * 8 + wid;             // exact: E = 200000*8

    float2 w2[4];
    #pragma unroll
    for (int t = 0; t < 4; ++t)
        w2[t] = reinterpret_cast<const float2*>(W2)[lane * 4 + t];

    int sn = src[e];
    int dn = dst[e];
    float4 pp = *reinterpret_cast<const float4*>(&p[(size_t)sn * 128 + lane * 4]);
    float4 qq = *reinterpret_cast<const float4*>(&q[(size_t)dn * 128 + lane * 4]);
    float h0 = fmaxf(pp.x + qq.x, 0.f);
    float h1 = fmaxf(pp.y + qq.y, 0.f);
    float h2 = fmaxf(pp.z + qq.z, 0.f);
    float h3 = fmaxf(pp.w + qq.w, 0.f);
    float s0 = h0 * w2[0].x + h1 * w2[1].x + h2 * w2[2].x + h3 * w2[3].x;
    float s1 = h0 * w2[0].y + h1 * w2[1].y + h2 * w2[2].y + h3 * w2[3].y;

    #pragma unroll
    for (int off = 16; off > 0; off >>= 1) {
        s0 += __shfl_xor_sync(0xffffffffu, s0, off);
        s1 += __shfl_xor_sync(0xffffffffu, s1, off);
    }
    if (lane == 0) {
        out[2 * (size_t)e]     = s0 + b2[0];
        out[2 * (size_t)e + 1] = s1 + b2[1];
    }
}

// ---------------- launch ----------------
extern "C" void kernel_launch(void* const* d_in, const int* in_sizes, int n_in,
                              void* d_out, int out_size)
{
    const float* nfeats = (const float*)d_in[0];
    const float* efeats = (const float*)d_in[1];
    const int*   src    = (const int*)  d_in[2];
    const int*   dst    = (const int*)  d_in[3];
    const float* Wm1 = (const float*)d_in[4];  const float* bm1 = (const float*)d_in[5];
    const float* Wa1 = (const float*)d_in[6];  const float* ba1 = (const float*)d_in[7];
    const float* Wm2 = (const float*)d_in[8];  const float* bm2 = (const float*)d_in[9];
    const float* Wa2 = (const float*)d_in[10]; const float* ba2 = (const float*)d_in[11];
    const float* W1  = (const float*)d_in[12]; const float* b1  = (const float*)d_in[13];
    const float* W2  = (const float*)d_in[14]; const float* b2  = (const float*)d_in[15];
    float* out = (float*)d_out;

    float *u, *s, *h1, *h2, *p, *q;
    cudaGetSymbolAddress((void**)&u,  g_u);
    cudaGetSymbolAddress((void**)&s,  g_s);
    cudaGetSymbolAddress((void**)&h1, g_h1);
    cudaGetSymbolAddress((void**)&h2, g_h2);
    cudaGetSymbolAddress((void**)&p,  g_p);
    cudaGetSymbolAddress((void**)&q,  g_q);

    const int GB = (NNODES + 127) / 128;      // 391 gemm blocks
    const int ZB = NNODES * 128 / 4 / 256;    // 6250 zero blocks (exact)
    const int EB = NEDGES / 128;              // 12500 edge-gemm blocks (exact)
    const int CB = NEDGES / 256;              // 6250 count blocks (exact)
    const int NB = (NNODES + 255) / 256;      // 196

    // Order chosen so k_edge is the 4th launch (ncu capture index 3).
    k_zero_f4<<<ZB, 256>>>(s);                                        // 0
    k_gemm<<<GB, 256>>>(nfeats, 64, nullptr, 0, 0, Wm1, bm1, u, 0);   // 1
    k_zero_cnt<<<NB, 256>>>();                                        // 2
    k_edge<<<EB, 256>>>(efeats, src, dst, Wm1 + 64 * 128, u, s);      // 3 (captured)
    k_count<<<CB, 256>>>(dst);                                        // 4
    k_inv<<<NB, 256>>>();                                             // 5
    k_gemm<<<GB, 256>>>(nfeats, 64, s, 128, 1, Wa1, ba1, h1, 1);      // 6

    // ---- SAGE layer 2 ----
    k_zero_f4<<<ZB, 256>>>(s);
    k_gemm<<<GB, 256>>>(h1, 128, nullptr, 0, 0, Wm2, bm2, u, 0);
    k_edge<<<EB, 256>>>(efeats, src, dst, Wm2 + 128 * 128, u, s);
    k_gemm<<<GB, 256>>>(h1, 128, s, 128, 1, Wa2, ba2, h2, 1);

    // ---- predictor ----
    k_gemm<<<GB, 256>>>(h2, 128, nullptr, 0, 0, W1, b1, p, 0);
    k_gemm<<<GB, 256>>>(h2, 128, nullptr, 0, 0, W1 + 128 * 128, nullptr, q, 0);
    k_pred<<<NEDGES / 8, 256>>>(src, dst, p, q, W2, b2, out);
}